// round 16
// baseline (speedup 1.0000x reference)
#include <cuda_runtime.h>
#include <cuda_bf16.h>

// Sparsemax over last dim, rows of N=1024 fp32.
// One WARP per row; 32 elements/thread in registers (measured-best config:
// regs~64, occ~39%, full 8xLDG.128 burst -> DRAM at the mixed-R/W wall).
// Residue trims this round: warp max via one REDUX.MAX (monotonic int
// transform) instead of a 5-deep shuffle chain; c-bounded all-pairs loop.

static constexpr int N = 1024;
static constexpr int THREADS = 256;            // 8 warps -> 8 rows per block
static constexpr int WARPS = THREADS / 32;
static constexpr int EPT = N / 32;             // 32 elements per thread
static constexpr int CAP = 128;                // candidate buffer per warp

// order-preserving float<->uint transform (total order, incl. sign)
__device__ __forceinline__ unsigned f2mono(float f) {
    unsigned u = __float_as_uint(f);
    return (u & 0x80000000u) ? ~u : (u | 0x80000000u);
}
__device__ __forceinline__ float mono2f(unsigned u) {
    u = (u & 0x80000000u) ? (u & 0x7FFFFFFFu) : ~u;
    return __uint_as_float(u);
}

__global__ __launch_bounds__(THREADS, 4)
void sparsemax_kernel(const float* __restrict__ x, float* __restrict__ out) {
    __shared__ float cand[WARPS][CAP];

    const int lane = threadIdx.x & 31;
    const int w    = threadIdx.x >> 5;
    float* __restrict__ my_cand = cand[w];
    const int row  = blockIdx.x * WARPS + w;
    const size_t base = (size_t)row * N;

    const float4* __restrict__ xr  = reinterpret_cast<const float4*>(x + base);
    float4*       __restrict__ orw = reinterpret_cast<float4*>(out + base);

    // ---- load row: 8 x float4 per thread, coalesced, front-batched ----
    float4 d[EPT / 4];
    #pragma unroll
    for (int i = 0; i < EPT / 4; ++i) d[i] = xr[lane + 32 * i];

    // ---- warp max: thread-local max, then one REDUX.MAX ----
    float tm = -3.402823466e38f;
    #pragma unroll
    for (int i = 0; i < EPT / 4; ++i)
        tm = fmaxf(tm, fmaxf(fmaxf(d[i].x, d[i].y), fmaxf(d[i].z, d[i].w)));
    const float m = mono2f(__reduce_max_sync(0xFFFFFFFFu, f2mono(tm)));

    // tau in [-1, 0): support subset of {x > m - 1}
    const float thr = m - 1.0f;

    // ---- per-thread candidate count ----
    unsigned cnt = 0;
    #pragma unroll
    for (int i = 0; i < EPT / 4; ++i) {
        cnt += (d[i].x > thr);
        cnt += (d[i].y > thr);
        cnt += (d[i].z > thr);
        cnt += (d[i].w > thr);
    }

    // ---- warp exclusive scan of counts (lane-major candidate order) ----
    unsigned incl = cnt;
    #pragma unroll
    for (int o = 1; o < 32; o <<= 1) {
        unsigned t = __shfl_up_sync(0xFFFFFFFFu, incl, o);
        if (lane >= o) incl += t;
    }
    const int c = (int)__shfl_sync(0xFFFFFFFFu, incl, 31);  // total candidates
    int idx = (int)(incl - cnt);                            // exclusive prefix

    // ---- write candidates (z = x - m) at scanned offsets ----
    if (c <= CAP) {
        #pragma unroll
        for (int i = 0; i < EPT / 4; ++i) {
            const float vv[4] = { d[i].x, d[i].y, d[i].z, d[i].w };
            #pragma unroll
            for (int j = 0; j < 4; ++j)
                if (vv[j] > thr) my_cand[idx++] = vv[j] - m;
        }
    }
    __syncwarp();

    float tau;
    if (c <= 32) {
        // ---- fast path: one candidate per lane, all-pairs via shuffles ----
        // lane s holds v_s (s < c). rank r_s = #{j : v_j > v_s or (==, j<=s)},
        // S_s = sum of those. cond_s = (1 + r_s*v_s > S_s).
        // k = max cond rank; num = sum cond*v; tau = (num - 1)/k.
        float v = (lane < c) ? my_cand[lane] : 0.0f;
        float S = 0.0f, r = 0.0f;
        #pragma unroll 1
        for (int j = 0; j < c; ++j) {
            float u = __shfl_sync(0xFFFFFFFFu, v, j);
            bool ge = (u > v) || (u == v && j <= lane);
            if (ge) { S += u; r += 1.0f; }
        }
        bool cond = (lane < c) && (1.0f + r * v > S);
        unsigned rr = cond ? (unsigned)r : 0u;
        float   num = cond ? v : 0.0f;
        unsigned kmax = __reduce_max_sync(0xFFFFFFFFu, rr);
        #pragma unroll
        for (int o = 16; o > 0; o >>= 1)
            num += __shfl_xor_sync(0xFFFFFFFFu, num, o);
        tau = (num - 1.0f) / (float)kmax;
    } else if (c <= CAP) {
        // ---- smem path: rank r and prefix-ordered sum S per slot ----
        unsigned kmax = 0u;
        float num = 0.0f;
        for (int slot = lane; slot < c; slot += 32) {
            const float v = my_cand[slot];
            float S = 0.0f, r = 0.0f;
            for (int j = 0; j < c; ++j) {
                const float u = my_cand[j];
                bool ge = (u > v) || (u == v && j <= slot);
                if (ge) { S += u; r += 1.0f; }
            }
            if (1.0f + r * v > S) {
                if ((unsigned)r > kmax) kmax = (unsigned)r;
                num += v;
            }
        }
        kmax = __reduce_max_sync(0xFFFFFFFFu, kmax);
        #pragma unroll
        for (int o = 16; o > 0; o >>= 1)
            num += __shfl_xor_sync(0xFFFFFFFFu, num, o);
        tau = (num - 1.0f) / (float)kmax;
    } else {
        // ---- fallback (essentially never taken): warp-local Michelot ----
        float s = 0.0f;
        #pragma unroll
        for (int i = 0; i < EPT / 4; ++i)
            s += ((d[i].x - m) + (d[i].y - m)) + ((d[i].z - m) + (d[i].w - m));
        #pragma unroll
        for (int o = 16; o > 0; o >>= 1)
            s += __shfl_xor_sync(0xFFFFFFFFu, s, o);
        tau = (s - 1.0f) / (float)N;
        float prev_k = (float)N;
        #pragma unroll 1
        for (int it = 0; it < 64; ++it) {
            float ps = 0.0f, pk = 0.0f;
            #pragma unroll
            for (int i = 0; i < EPT / 4; ++i) {
                const float vv[4] = { d[i].x - m, d[i].y - m, d[i].z - m, d[i].w - m };
                #pragma unroll
                for (int j = 0; j < 4; ++j)
                    if (vv[j] > tau) { ps += vv[j]; pk += 1.0f; }
            }
            #pragma unroll
            for (int o = 16; o > 0; o >>= 1) {
                ps += __shfl_xor_sync(0xFFFFFFFFu, ps, o);
                pk += __shfl_xor_sync(0xFFFFFFFFu, pk, o);
            }
            float k = (pk > 0.0f) ? pk : 1.0f;
            float nt = (ps - 1.0f) / k;
            bool done = (nt == tau) && (k == prev_k);
            tau = nt;
            prev_k = k;
            if (done) break;
        }
    }

    // ---- output: max(x - (m + tau), 0) ----
    const float t2 = m + tau;
    #pragma unroll
    for (int i = 0; i < EPT / 4; ++i) {
        float4 o;
        o.x = fmaxf(d[i].x - t2, 0.0f);
        o.y = fmaxf(d[i].y - t2, 0.0f);
        o.z = fmaxf(d[i].z - t2, 0.0f);
        o.w = fmaxf(d[i].w - t2, 0.0f);
        orw[lane + 32 * i] = o;
    }
}

extern "C" void kernel_launch(void* const* d_in, const int* in_sizes, int n_in,
                              void* d_out, int out_size) {
    const float* x = (const float*)d_in[0];
    float* out = (float*)d_out;
    int rows = in_sizes[0] / N;
    sparsemax_kernel<<<rows / WARPS, THREADS>>>(x, out);
}

// round 17
// speedup vs baseline: 1.0251x; 1.0251x over previous
#include <cuda_runtime.h>
#include <cuda_bf16.h>

// Sparsemax over last dim, rows of N=1024 fp32.
// One WARP per row; 32 elements/thread in registers (measured-best config:
// regs~64, occ~37%, full 8xLDG.128 burst -> mixed-R/W DRAM wall ~63%).
// Single-variable change vs R16: streaming cache hints (__ldcs/__stcs) on
// the once-touched input/output streams to cut L2 read/write thrash.
// tau: scan-compaction of candidates {x > max-1}; REDUX warp max; shuffle
// all-pairs closed-form solve for c<=32; smem path to 128; Michelot beyond.

static constexpr int N = 1024;
static constexpr int THREADS = 256;            // 8 warps -> 8 rows per block
static constexpr int WARPS = THREADS / 32;
static constexpr int EPT = N / 32;             // 32 elements per thread
static constexpr int CAP = 128;                // candidate buffer per warp

// order-preserving float<->uint transform (total order, incl. sign)
__device__ __forceinline__ unsigned f2mono(float f) {
    unsigned u = __float_as_uint(f);
    return (u & 0x80000000u) ? ~u : (u | 0x80000000u);
}
__device__ __forceinline__ float mono2f(unsigned u) {
    u = (u & 0x80000000u) ? (u & 0x7FFFFFFFu) : ~u;
    return __uint_as_float(u);
}

__global__ __launch_bounds__(THREADS, 4)
void sparsemax_kernel(const float* __restrict__ x, float* __restrict__ out) {
    __shared__ float cand[WARPS][CAP];

    const int lane = threadIdx.x & 31;
    const int w    = threadIdx.x >> 5;
    float* __restrict__ my_cand = cand[w];
    const int row  = blockIdx.x * WARPS + w;
    const size_t base = (size_t)row * N;

    const float4* __restrict__ xr  = reinterpret_cast<const float4*>(x + base);
    float4*       __restrict__ orw = reinterpret_cast<float4*>(out + base);

    // ---- load row: 8 x LDG.128 (streaming, evict-first), front-batched ----
    float4 d[EPT / 4];
    #pragma unroll
    for (int i = 0; i < EPT / 4; ++i) d[i] = __ldcs(&xr[lane + 32 * i]);

    // ---- warp max: thread-local max, then one REDUX.MAX ----
    float tm = -3.402823466e38f;
    #pragma unroll
    for (int i = 0; i < EPT / 4; ++i)
        tm = fmaxf(tm, fmaxf(fmaxf(d[i].x, d[i].y), fmaxf(d[i].z, d[i].w)));
    const float m = mono2f(__reduce_max_sync(0xFFFFFFFFu, f2mono(tm)));

    // tau in [-1, 0): support subset of {x > m - 1}
    const float thr = m - 1.0f;

    // ---- per-thread candidate count ----
    unsigned cnt = 0;
    #pragma unroll
    for (int i = 0; i < EPT / 4; ++i) {
        cnt += (d[i].x > thr);
        cnt += (d[i].y > thr);
        cnt += (d[i].z > thr);
        cnt += (d[i].w > thr);
    }

    // ---- warp exclusive scan of counts (lane-major candidate order) ----
    unsigned incl = cnt;
    #pragma unroll
    for (int o = 1; o < 32; o <<= 1) {
        unsigned t = __shfl_up_sync(0xFFFFFFFFu, incl, o);
        if (lane >= o) incl += t;
    }
    const int c = (int)__shfl_sync(0xFFFFFFFFu, incl, 31);  // total candidates
    int idx = (int)(incl - cnt);                            // exclusive prefix

    // ---- write candidates (z = x - m) at scanned offsets ----
    if (c <= CAP) {
        #pragma unroll
        for (int i = 0; i < EPT / 4; ++i) {
            const float vv[4] = { d[i].x, d[i].y, d[i].z, d[i].w };
            #pragma unroll
            for (int j = 0; j < 4; ++j)
                if (vv[j] > thr) my_cand[idx++] = vv[j] - m;
        }
    }
    __syncwarp();

    float tau;
    if (c <= 32) {
        // ---- fast path: one candidate per lane, all-pairs via shuffles ----
        float v = (lane < c) ? my_cand[lane] : 0.0f;
        float S = 0.0f, r = 0.0f;
        #pragma unroll 1
        for (int j = 0; j < c; ++j) {
            float u = __shfl_sync(0xFFFFFFFFu, v, j);
            bool ge = (u > v) || (u == v && j <= lane);
            if (ge) { S += u; r += 1.0f; }
        }
        bool cond = (lane < c) && (1.0f + r * v > S);
        unsigned rr = cond ? (unsigned)r : 0u;
        float   num = cond ? v : 0.0f;
        unsigned kmax = __reduce_max_sync(0xFFFFFFFFu, rr);
        #pragma unroll
        for (int o = 16; o > 0; o >>= 1)
            num += __shfl_xor_sync(0xFFFFFFFFu, num, o);
        tau = (num - 1.0f) / (float)kmax;
    } else if (c <= CAP) {
        // ---- smem path: rank r and prefix-ordered sum S per slot ----
        unsigned kmax = 0u;
        float num = 0.0f;
        for (int slot = lane; slot < c; slot += 32) {
            const float v = my_cand[slot];
            float S = 0.0f, r = 0.0f;
            for (int j = 0; j < c; ++j) {
                const float u = my_cand[j];
                bool ge = (u > v) || (u == v && j <= slot);
                if (ge) { S += u; r += 1.0f; }
            }
            if (1.0f + r * v > S) {
                if ((unsigned)r > kmax) kmax = (unsigned)r;
                num += v;
            }
        }
        kmax = __reduce_max_sync(0xFFFFFFFFu, kmax);
        #pragma unroll
        for (int o = 16; o > 0; o >>= 1)
            num += __shfl_xor_sync(0xFFFFFFFFu, num, o);
        tau = (num - 1.0f) / (float)kmax;
    } else {
        // ---- fallback (essentially never taken): warp-local Michelot ----
        float s = 0.0f;
        #pragma unroll
        for (int i = 0; i < EPT / 4; ++i)
            s += ((d[i].x - m) + (d[i].y - m)) + ((d[i].z - m) + (d[i].w - m));
        #pragma unroll
        for (int o = 16; o > 0; o >>= 1)
            s += __shfl_xor_sync(0xFFFFFFFFu, s, o);
        tau = (s - 1.0f) / (float)N;
        float prev_k = (float)N;
        #pragma unroll 1
        for (int it = 0; it < 64; ++it) {
            float ps = 0.0f, pk = 0.0f;
            #pragma unroll
            for (int i = 0; i < EPT / 4; ++i) {
                const float vv[4] = { d[i].x - m, d[i].y - m, d[i].z - m, d[i].w - m };
                #pragma unroll
                for (int j = 0; j < 4; ++j)
                    if (vv[j] > tau) { ps += vv[j]; pk += 1.0f; }
            }
            #pragma unroll
            for (int o = 16; o > 0; o >>= 1) {
                ps += __shfl_xor_sync(0xFFFFFFFFu, ps, o);
                pk += __shfl_xor_sync(0xFFFFFFFFu, pk, o);
            }
            float k = (pk > 0.0f) ? pk : 1.0f;
            float nt = (ps - 1.0f) / k;
            bool done = (nt == tau) && (k == prev_k);
            tau = nt;
            prev_k = k;
            if (done) break;
        }
    }

    // ---- output: max(x - (m + tau), 0), streaming stores ----
    const float t2 = m + tau;
    #pragma unroll
    for (int i = 0; i < EPT / 4; ++i) {
        float4 o;
        o.x = fmaxf(d[i].x - t2, 0.0f);
        o.y = fmaxf(d[i].y - t2, 0.0f);
        o.z = fmaxf(d[i].z - t2, 0.0f);
        o.w = fmaxf(d[i].w - t2, 0.0f);
        __stcs(&orw[lane + 32 * i], o);
    }
}

extern "C" void kernel_launch(void* const* d_in, const int* in_sizes, int n_in,
                              void* d_out, int out_size) {
    const float* x = (const float*)d_in[0];
    float* out = (float*)d_out;
    int rows = in_sizes[0] / N;
    sparsemax_kernel<<<rows / WARPS, THREADS>>>(x, out);
}